// round 1
// baseline (speedup 1.0000x reference)
#include <cuda_runtime.h>
#include <math.h>

// Problem shape (fixed by setup_inputs): B=2, H=16, S=2048, D=128, BLOCK=256
#define S_LEN 2048
#define D_DIM 128
#define BSK   256      // key block size (per-block softmax width)
#define SQ    64       // q rows per CTA
#define HK    128      // kv half-tile rows
#define BH_MAX 32      // B*H

// smem layout (floats)
#define QT_STRIDE 68                   // padded row stride for qT[d][r]
#define KV_STRIDE 132                  // padded row stride for kv tile
#define SC_STRIDE 260                  // padded row stride for score tile
#define QT_FLOATS (D_DIM * QT_STRIDE)              // 8704
#define KV_FLOATS (HK * KV_STRIDE)                 // 16896
#define SC_FLOATS (SQ * SC_STRIDE)                 // 16640
#define SMEM_FLOATS (QT_FLOATS + KV_FLOATS + SC_FLOATS)  // 42240 -> 168960 B

typedef unsigned long long ull;

// Packed fp32x2 FMA (Blackwell sm_100+): d = a*b + c on two lanes at once.
#define FMA_F32X2(d, a, b, c) \
    asm("fma.rn.f32x2 %0, %1, %2, %3;" : "=l"(d) : "l"(a), "l"(b), "l"(c))

// Broadcast one fp32 into both halves of a b64.
#define PACK2(d, x) \
    asm("mov.b64 %0, {%1, %1};" : "=l"(d) : "r"(__float_as_uint(x)))

// Scratch: K transposed to [bh][d][s] so score-GEMM loads are coalesced/pair-friendly.
__device__ float g_KT[BH_MAX * S_LEN * D_DIM];

// ---------------------------------------------------------------------------
// K transpose: KT[bh][d][s] = K[bh][s][d]
// ---------------------------------------------------------------------------
__global__ void transpose_k_kernel(const float* __restrict__ K) {
    __shared__ float tile[32][33];
    const int s0 = blockIdx.x * 32;
    const int d0 = blockIdx.y * 32;
    const int b  = blockIdx.z;
    const float* Kb = K + (size_t)b * S_LEN * D_DIM;
    float* KTb = g_KT + (size_t)b * S_LEN * D_DIM;

    #pragma unroll
    for (int i = threadIdx.y; i < 32; i += 8)
        tile[i][threadIdx.x] = Kb[(size_t)(s0 + i) * D_DIM + d0 + threadIdx.x];
    __syncthreads();
    #pragma unroll
    for (int i = threadIdx.y; i < 32; i += 8)
        KTb[(size_t)(d0 + i) * S_LEN + s0 + threadIdx.x] = tile[threadIdx.x][i];
}

// ---------------------------------------------------------------------------
// Blocked attention: per (bh, 64-row q block) CTA.
// For each key block j (256 keys): scores = q@k^T, per-row softmax over the
// 256 keys of THIS block only, out += w@v. Accumulate out across j in regs.
// ---------------------------------------------------------------------------
__global__ __launch_bounds__(256, 1)
void attn_kernel(const float* __restrict__ Q,
                 const float* __restrict__ V,
                 float* __restrict__ O) {
    extern __shared__ float sm[];
    float* qT = sm;                       // [D][QT_STRIDE], qT[d][r]
    float* kv = sm + QT_FLOATS;           // staging: kT half [128][KV_STRIDE] or v half [128][KV_STRIDE]
    float* sc = sm + QT_FLOATS + KV_FLOATS; // scores [64][SC_STRIDE]

    const int bh = blockIdx.y;
    const int qb = blockIdx.x;
    const int tid = threadIdx.x;
    const int ty = tid >> 4;    // 0..15 -> 4 q rows each
    const int tx = tid & 15;    // 0..15 -> 8 k cols / 8 d cols each

    const size_t bhoff = (size_t)bh * S_LEN * D_DIM;
    const float* Qb  = Q + bhoff + (size_t)qb * SQ * D_DIM;
    const float* KTb = g_KT + bhoff;      // [D][S]
    const float* Vb  = V + bhoff;         // [S][D]
    float* Ob = O + bhoff + (size_t)qb * SQ * D_DIM;

    // ---- load Q block, transposed into qT[d][r] ----
    #pragma unroll
    for (int ii = 0; ii < 8; ii++) {
        int f4 = tid + 256 * ii;              // 0..2047
        int r  = f4 >> 5;                     // 0..63
        int d4 = (f4 & 31) << 2;              // 0..124
        float4 v4 = *(const float4*)(Qb + (size_t)r * D_DIM + d4);
        qT[(d4 + 0) * QT_STRIDE + r] = v4.x;
        qT[(d4 + 1) * QT_STRIDE + r] = v4.y;
        qT[(d4 + 2) * QT_STRIDE + r] = v4.z;
        qT[(d4 + 3) * QT_STRIDE + r] = v4.w;
    }

    // output accumulators: 4 q rows x 8 d cols as 4x4 packed pairs
    ull oacc[4][4];
    #pragma unroll
    for (int r = 0; r < 4; r++)
        #pragma unroll
        for (int p = 0; p < 4; p++) oacc[r][p] = 0ull;

    const float cexp = 0.088388347648318440878f * 1.44269504088896340736f; // D^-0.5 * log2(e)

    for (int jb = 0; jb < (S_LEN / BSK); jb++) {
        // ================= scores: two 128-col halves =================
        #pragma unroll 1
        for (int h = 0; h < 2; h++) {
            __syncthreads();   // kv buffer free
            {
                const float* src = KTb + (size_t)(jb * BSK + h * HK);
                #pragma unroll
                for (int ii = 0; ii < 16; ii++) {
                    int f4 = tid + 256 * ii;      // 0..4095
                    int d  = f4 >> 5;             // 0..127
                    int c4 = (f4 & 31) << 2;      // 0..124
                    *(float4*)&kv[d * KV_STRIDE + c4] =
                        *(const float4*)(src + (size_t)d * S_LEN + c4);
                }
            }
            __syncthreads();

            ull a2[4][4];
            #pragma unroll
            for (int r = 0; r < 4; r++)
                #pragma unroll
                for (int p = 0; p < 4; p++) a2[r][p] = 0ull;

            const float* qcol = qT + ty * 4;
            const float* kcol = kv + tx * 8;
            #pragma unroll 4
            for (int d = 0; d < D_DIM; d++) {
                float4 qv = *(const float4*)(qcol + d * QT_STRIDE);
                ull q0, q1, q2, q3;
                PACK2(q0, qv.x); PACK2(q1, qv.y); PACK2(q2, qv.z); PACK2(q3, qv.w);
                const ull* kp = (const ull*)(kcol + d * KV_STRIDE); // 4 pairs (8 floats)
                ull k0 = kp[0], k1 = kp[1], k2 = kp[2], k3 = kp[3];
                FMA_F32X2(a2[0][0], q0, k0, a2[0][0]);
                FMA_F32X2(a2[0][1], q0, k1, a2[0][1]);
                FMA_F32X2(a2[0][2], q0, k2, a2[0][2]);
                FMA_F32X2(a2[0][3], q0, k3, a2[0][3]);
                FMA_F32X2(a2[1][0], q1, k0, a2[1][0]);
                FMA_F32X2(a2[1][1], q1, k1, a2[1][1]);
                FMA_F32X2(a2[1][2], q1, k2, a2[1][2]);
                FMA_F32X2(a2[1][3], q1, k3, a2[1][3]);
                FMA_F32X2(a2[2][0], q2, k0, a2[2][0]);
                FMA_F32X2(a2[2][1], q2, k1, a2[2][1]);
                FMA_F32X2(a2[2][2], q2, k2, a2[2][2]);
                FMA_F32X2(a2[2][3], q2, k3, a2[2][3]);
                FMA_F32X2(a2[3][0], q3, k0, a2[3][0]);
                FMA_F32X2(a2[3][1], q3, k1, a2[3][1]);
                FMA_F32X2(a2[3][2], q3, k2, a2[3][2]);
                FMA_F32X2(a2[3][3], q3, k3, a2[3][3]);
            }
            // store raw scores (scale folded into softmax exponent)
            #pragma unroll
            for (int r = 0; r < 4; r++) {
                ull* srow = (ull*)&sc[(ty * 4 + r) * SC_STRIDE + h * HK + tx * 8];
                #pragma unroll
                for (int p = 0; p < 4; p++) srow[p] = a2[r][p];
            }
        }
        __syncthreads();   // score tile complete

        // ================= per-row softmax over 256 cols =================
        {
            const int row  = tid >> 2;
            const int part = tid & 3;
            float* srow = sc + row * SC_STRIDE + part * 64;

            float m = -INFINITY;
            #pragma unroll
            for (int ii = 0; ii < 16; ii++) {
                float4 x = ((const float4*)srow)[ii];
                m = fmaxf(m, fmaxf(fmaxf(x.x, x.y), fmaxf(x.z, x.w)));
            }
            m = fmaxf(m, __shfl_xor_sync(0xffffffffu, m, 1));
            m = fmaxf(m, __shfl_xor_sync(0xffffffffu, m, 2));

            float ssum = 0.0f;
            #pragma unroll
            for (int ii = 0; ii < 16; ii++) {
                float4 x = ((const float4*)srow)[ii];
                x.x = exp2f((x.x - m) * cexp);
                x.y = exp2f((x.y - m) * cexp);
                x.z = exp2f((x.z - m) * cexp);
                x.w = exp2f((x.w - m) * cexp);
                ssum += (x.x + x.y) + (x.z + x.w);
                ((float4*)srow)[ii] = x;
            }
            ssum += __shfl_xor_sync(0xffffffffu, ssum, 1);
            ssum += __shfl_xor_sync(0xffffffffu, ssum, 2);
            float inv = 1.0f / ssum;
            #pragma unroll
            for (int ii = 0; ii < 16; ii++) {
                float4 x = ((const float4*)srow)[ii];
                x.x *= inv; x.y *= inv; x.z *= inv; x.w *= inv;
                ((float4*)srow)[ii] = x;
            }
        }

        // ================= PV: two 128-key halves =================
        #pragma unroll 1
        for (int h = 0; h < 2; h++) {
            __syncthreads();   // kv free; softmax writes visible after this sync
            {
                const float* src = Vb + (size_t)(jb * BSK + h * HK) * D_DIM;
                #pragma unroll
                for (int ii = 0; ii < 16; ii++) {
                    int f4 = tid + 256 * ii;
                    int kk = f4 >> 5;
                    int c4 = (f4 & 31) << 2;
                    *(float4*)&kv[kk * KV_STRIDE + c4] =
                        *(const float4*)(src + (size_t)kk * D_DIM + c4);
                }
            }
            __syncthreads();

            const float* wbase = sc + (ty * 4) * SC_STRIDE + h * HK;
            const float* vcol  = kv + tx * 8;
            #pragma unroll 4
            for (int kk = 0; kk < HK; kk++) {
                float w0 = wbase[0 * SC_STRIDE + kk];
                float w1 = wbase[1 * SC_STRIDE + kk];
                float w2 = wbase[2 * SC_STRIDE + kk];
                float w3 = wbase[3 * SC_STRIDE + kk];
                ull p0, p1, p2, p3;
                PACK2(p0, w0); PACK2(p1, w1); PACK2(p2, w2); PACK2(p3, w3);
                const ull* vp = (const ull*)(vcol + kk * KV_STRIDE); // 4 pairs
                ull v0 = vp[0], v1 = vp[1], v2 = vp[2], v3 = vp[3];
                FMA_F32X2(oacc[0][0], p0, v0, oacc[0][0]);
                FMA_F32X2(oacc[0][1], p0, v1, oacc[0][1]);
                FMA_F32X2(oacc[0][2], p0, v2, oacc[0][2]);
                FMA_F32X2(oacc[0][3], p0, v3, oacc[0][3]);
                FMA_F32X2(oacc[1][0], p1, v0, oacc[1][0]);
                FMA_F32X2(oacc[1][1], p1, v1, oacc[1][1]);
                FMA_F32X2(oacc[1][2], p1, v2, oacc[1][2]);
                FMA_F32X2(oacc[1][3], p1, v3, oacc[1][3]);
                FMA_F32X2(oacc[2][0], p2, v0, oacc[2][0]);
                FMA_F32X2(oacc[2][1], p2, v1, oacc[2][1]);
                FMA_F32X2(oacc[2][2], p2, v2, oacc[2][2]);
                FMA_F32X2(oacc[2][3], p2, v3, oacc[2][3]);
                FMA_F32X2(oacc[3][0], p3, v0, oacc[3][0]);
                FMA_F32X2(oacc[3][1], p3, v1, oacc[3][1]);
                FMA_F32X2(oacc[3][2], p3, v2, oacc[3][2]);
                FMA_F32X2(oacc[3][3], p3, v3, oacc[3][3]);
            }
        }
    }

    // ---- write output: rows ty*4+r, cols tx*8..tx*8+7 ----
    #pragma unroll
    for (int r = 0; r < 4; r++) {
        int qr = ty * 4 + r;
        float2 a = *(float2*)&oacc[r][0];
        float2 b = *(float2*)&oacc[r][1];
        float2 c = *(float2*)&oacc[r][2];
        float2 d = *(float2*)&oacc[r][3];
        float4 lo = make_float4(a.x, a.y, b.x, b.y);
        float4 hi = make_float4(c.x, c.y, d.x, d.y);
        float* dst = Ob + (size_t)qr * D_DIM + tx * 8;
        ((float4*)dst)[0] = lo;
        ((float4*)dst)[1] = hi;
    }
}

// ---------------------------------------------------------------------------
extern "C" void kernel_launch(void* const* d_in, const int* in_sizes, int n_in,
                              void* d_out, int out_size) {
    const float* Q = (const float*)d_in[0];
    const float* K = (const float*)d_in[1];
    const float* V = (const float*)d_in[2];
    float* O = (float*)d_out;

    const int bh = in_sizes[0] / (S_LEN * D_DIM);   // 32 for B=2,H=16

    // 1) transpose K into g_KT
    transpose_k_kernel<<<dim3(S_LEN / 32, D_DIM / 32, bh), dim3(32, 8)>>>(K);

    // 2) blocked attention
    const size_t smem_bytes = (size_t)SMEM_FLOATS * sizeof(float);
    cudaFuncSetAttribute(attn_kernel, cudaFuncAttributeMaxDynamicSharedMemorySize,
                         (int)smem_bytes);
    attn_kernel<<<dim3(S_LEN / SQ, bh), 256, smem_bytes>>>(Q, V, O);
}

// round 3
// speedup vs baseline: 2.7150x; 2.7150x over previous
#include <cuda_runtime.h>
#include <cstdint>
#include <math.h>

// Shape fixed by setup_inputs: B=2, H=16, S=2048, D=128, key block = 256
#define S_LEN 2048
#define D_DIM 128

#define SQ 64            // q rows per CTA
#define KV_STRIDE 136    // padded floats per KV tile row (conflict-free, see notes)
#define SC_STRIDE 260    // padded floats per score row
#define SC_FLOATS (SQ * SC_STRIDE)        // 16640
#define KV_FLOATS (128 * KV_STRIDE)       // 17408
#define SMEM_FLOATS (SC_FLOATS + 2 * KV_FLOATS)   // 51456 -> 205824 B

__device__ __forceinline__ uint32_t tf32b(float x) {
    uint32_t u; asm("cvt.rna.tf32.f32 %0, %1;" : "=r"(u) : "f"(x)); return u;
}
__device__ __forceinline__ float tf32r(float x) { return __uint_as_float(tf32b(x)); }

// m16n8k8 tf32 HMMA, D += A*B
__device__ __forceinline__ void mma8(float* c, uint32_t a0, uint32_t a1,
                                     uint32_t a2, uint32_t a3,
                                     uint32_t b0, uint32_t b1) {
    asm volatile(
        "mma.sync.aligned.m16n8k8.row.col.f32.tf32.tf32.f32 "
        "{%0,%1,%2,%3}, {%4,%5,%6,%7}, {%8,%9}, {%0,%1,%2,%3};"
        : "+f"(c[0]), "+f"(c[1]), "+f"(c[2]), "+f"(c[3])
        : "r"(a0), "r"(a1), "r"(a2), "r"(a3), "r"(b0), "r"(b1));
}

// Stage a 128x128 f32 tile (row stride D_DIM in gmem) into smem with
// KV_STRIDE padding, rounding to tf32 (rna). 256 threads.
__device__ __forceinline__ void stage_kv(float* dst, const float* __restrict__ src,
                                         int tid) {
    #pragma unroll
    for (int i = 0; i < 16; i++) {
        int idx = tid + 256 * i;          // 0..4095
        int r = idx >> 5;                 // 0..127
        int c4 = (idx & 31) << 2;         // 0..124
        float4 v = *(const float4*)(src + (size_t)r * D_DIM + c4);
        v.x = tf32r(v.x); v.y = tf32r(v.y); v.z = tf32r(v.z); v.w = tf32r(v.w);
        *(float4*)(dst + r * KV_STRIDE + c4) = v;
    }
}

// ---------------------------------------------------------------------------
// Blocked attention, warp-level tf32 tensor cores.
// CTA: 64 q rows. 8 warps = 4(M:16 rows) x 2(N/D half:128 keys / 64 dims).
// Per key block jb (256 keys): S = Q K^T -> smem, per-row softmax over the
// 256 keys of this block, O += P V, O frags held in regs across jb.
// ---------------------------------------------------------------------------
__global__ __launch_bounds__(256, 1)
void attn_mma_kernel(const float* __restrict__ Q,
                     const float* __restrict__ K,
                     const float* __restrict__ V,
                     float* __restrict__ O) {
    extern __shared__ float sm[];
    float* sc = sm;                       // [64][SC_STRIDE]
    float* b0 = sm + SC_FLOATS;           // [128][KV_STRIDE]
    float* b1 = b0 + KV_FLOATS;           // [128][KV_STRIDE]

    const int tid  = threadIdx.x;
    const int wid  = tid >> 5;
    const int lane = tid & 31;
    const int m = wid & 3;                // M block (16 rows)
    const int h = wid >> 2;               // N half (QK: keys 128h..; PV: dims 64h..)
    const int g = lane >> 2;              // group row 0..7
    const int t = lane & 3;               // thread-in-group 0..3

    const int bh = blockIdx.y;
    const int qb = blockIdx.x;
    const size_t bhoff = (size_t)bh * S_LEN * D_DIM;
    const float* Qb = Q + bhoff + (size_t)qb * SQ * D_DIM;
    const float* Kb = K + bhoff;
    const float* Vb = V + bhoff;
    float* Ob = O + bhoff + (size_t)qb * SQ * D_DIM;

    // ---- Q A-fragments in registers: rows 16m+g(+8), cols ks*8+t(+4), tf32 ----
    uint32_t aq[16][4];
    {
        const float* q0 = Qb + (size_t)(16 * m + g) * D_DIM;
        const float* q1 = q0 + 8 * D_DIM;
        #pragma unroll
        for (int ks = 0; ks < 16; ks++) {
            int c = ks * 8 + t;
            aq[ks][0] = tf32b(q0[c]);
            aq[ks][1] = tf32b(q1[c]);
            aq[ks][2] = tf32b(q0[c + 4]);
            aq[ks][3] = tf32b(q1[c + 4]);
        }
    }

    // ---- O accumulators: warp tile 16 x 64 (8 n-tiles) ----
    float oacc[8][4];
    #pragma unroll
    for (int nt = 0; nt < 8; nt++)
        #pragma unroll
        for (int j = 0; j < 4; j++) oacc[nt][j] = 0.0f;

    const float cexp = 0.08838834764831845f * 1.4426950408889634f; // D^-0.5*log2(e)

    for (int jb = 0; jb < S_LEN / 256; jb++) {
        // ================= stage K (two 128-key chunks) =================
        stage_kv(b0, Kb + (size_t)(jb * 256) * D_DIM, tid);
        stage_kv(b1, Kb + (size_t)(jb * 256 + 128) * D_DIM, tid);
        __syncthreads();

        // ================= QK^T: warp tile 16 x 128 =================
        {
            float c[16][4];
            #pragma unroll
            for (int nt = 0; nt < 16; nt++)
                #pragma unroll
                for (int j = 0; j < 4; j++) c[nt][j] = 0.0f;

            const float* kb = h ? b1 : b0;
            #pragma unroll 4
            for (int ks = 0; ks < 16; ks++) {
                const float* kcol = kb + ks * 8 + t;   // d = ks*8+t
                #pragma unroll
                for (int nt = 0; nt < 16; nt++) {
                    // B: k=d (ks*8+t, +4), n=key (nt*8+g)
                    const float* kp = kcol + (nt * 8 + g) * KV_STRIDE;
                    uint32_t bb0 = __float_as_uint(kp[0]);
                    uint32_t bb1 = __float_as_uint(kp[4]);
                    mma8(c[nt], aq[ks][0], aq[ks][1], aq[ks][2], aq[ks][3], bb0, bb1);
                }
            }
            // store S: rows 16m+g(+8), cols 128h + nt*8 + 2t(+1)
            float* s0 = sc + (16 * m + g) * SC_STRIDE + 128 * h + 2 * t;
            float* s1 = s0 + 8 * SC_STRIDE;
            #pragma unroll
            for (int nt = 0; nt < 16; nt++) {
                *(float2*)(s0 + nt * 8) = make_float2(c[nt][0], c[nt][1]);
                *(float2*)(s1 + nt * 8) = make_float2(c[nt][2], c[nt][3]);
            }
        }
        __syncthreads();

        // ================= per-row softmax over 256 cols =================
        {
            const int row  = tid >> 2;
            const int part = tid & 3;
            float* srow = sc + row * SC_STRIDE + part * 64;

            float mx = -INFINITY;
            #pragma unroll
            for (int ii = 0; ii < 16; ii++) {
                float4 x = ((const float4*)srow)[ii];
                mx = fmaxf(mx, fmaxf(fmaxf(x.x, x.y), fmaxf(x.z, x.w)));
            }
            mx = fmaxf(mx, __shfl_xor_sync(0xffffffffu, mx, 1));
            mx = fmaxf(mx, __shfl_xor_sync(0xffffffffu, mx, 2));

            float ssum = 0.0f;
            #pragma unroll
            for (int ii = 0; ii < 16; ii++) {
                float4 x = ((const float4*)srow)[ii];
                x.x = exp2f((x.x - mx) * cexp);
                x.y = exp2f((x.y - mx) * cexp);
                x.z = exp2f((x.z - mx) * cexp);
                x.w = exp2f((x.w - mx) * cexp);
                ssum += (x.x + x.y) + (x.z + x.w);
                ((float4*)srow)[ii] = x;
            }
            ssum += __shfl_xor_sync(0xffffffffu, ssum, 1);
            ssum += __shfl_xor_sync(0xffffffffu, ssum, 2);
            float inv = 1.0f / ssum;
            #pragma unroll
            for (int ii = 0; ii < 16; ii++) {
                float4 x = ((const float4*)srow)[ii];
                x.x = tf32r(x.x * inv);
                x.y = tf32r(x.y * inv);
                x.z = tf32r(x.z * inv);
                x.w = tf32r(x.w * inv);
                ((float4*)srow)[ii] = x;
            }
        }
        __syncthreads();

        // ================= stage V (two 128-key chunks) =================
        stage_kv(b0, Vb + (size_t)(jb * 256) * D_DIM, tid);
        stage_kv(b1, Vb + (size_t)(jb * 256 + 128) * D_DIM, tid);
        __syncthreads();

        // ================= PV: O(16 x 64 per warp) += P V =================
        {
            const float* p0 = sc + (16 * m + g) * SC_STRIDE;
            const float* p1 = p0 + 8 * SC_STRIDE;
            #pragma unroll 1
            for (int kc = 0; kc < 2; kc++) {
                const float* vb = (kc ? b1 : b0) + 64 * h + g;  // n = 64h + nt*8 + g
                #pragma unroll 4
                for (int ks = 0; ks < 16; ks++) {
                    int kcol = kc * 128 + ks * 8 + t;           // key index
                    uint32_t ap0 = __float_as_uint(p0[kcol]);
                    uint32_t ap1 = __float_as_uint(p1[kcol]);
                    uint32_t ap2 = __float_as_uint(p0[kcol + 4]);
                    uint32_t ap3 = __float_as_uint(p1[kcol + 4]);
                    const float* vrow0 = vb + (ks * 8 + t) * KV_STRIDE;
                    #pragma unroll
                    for (int nt = 0; nt < 8; nt++) {
                        uint32_t bb0 = __float_as_uint(vrow0[nt * 8]);
                        uint32_t bb1 = __float_as_uint(vrow0[nt * 8 + 4 * KV_STRIDE]);
                        mma8(oacc[nt], ap0, ap1, ap2, ap3, bb0, bb1);
                    }
                }
            }
        }
        __syncthreads();   // b0/b1 + sc reads done before next jb overwrites
    }

    // ---- write O: rows 16m+g(+8), cols 64h + nt*8 + 2t(+1) ----
    {
        float* o0 = Ob + (size_t)(16 * m + g) * D_DIM + 64 * h + 2 * t;
        float* o1 = o0 + 8 * D_DIM;
        #pragma unroll
        for (int nt = 0; nt < 8; nt++) {
            *(float2*)(o0 + nt * 8) = make_float2(oacc[nt][0], oacc[nt][1]);
            *(float2*)(o1 + nt * 8) = make_float2(oacc[nt][2], oacc[nt][3]);
        }
    }
}

// ---------------------------------------------------------------------------
extern "C" void kernel_launch(void* const* d_in, const int* in_sizes, int n_in,
                              void* d_out, int out_size) {
    const float* Q = (const float*)d_in[0];
    const float* K = (const float*)d_in[1];
    const float* V = (const float*)d_in[2];
    float* O = (float*)d_out;

    const int bh = in_sizes[0] / (S_LEN * D_DIM);   // 32

    const size_t smem_bytes = (size_t)SMEM_FLOATS * sizeof(float);
    cudaFuncSetAttribute(attn_mma_kernel, cudaFuncAttributeMaxDynamicSharedMemorySize,
                         (int)smem_bytes);
    attn_mma_kernel<<<dim3(S_LEN / SQ, bh), 256, smem_bytes>>>(Q, K, V, O);
}